// round 7
// baseline (speedup 1.0000x reference)
#include <cuda_runtime.h>
#include <cuda_bf16.h>
#include <math.h>

#define Bn     4
#define Cc     256
#define Hh     128
#define Ww     128
#define HWn    16384
#define HEADSn 8
#define HDn    32
#define LINn   512
#define HIDn   680
#define MHn    128
#define NSPLIT 8

#define CHW    ((long)Cc*HWn)          // 4194304
#define NIMG   ((long)Bn*Cc*HWn)       // 16777216

// ------------------------- scratch (static device memory) -------------------
__device__ int   g_idx [Bn*LINn];
__device__ float g_pp  [Bn*MHn];
__device__ float g_Weff[Bn*Cc*Cc];
__device__ float g_beff[Bn*Cc];
__device__ float g_kn  [Bn*Cc*HWn];
__device__ float g_qn  [Bn*Cc*HWn];
__device__ float g_q   [Bn*Cc*HWn];
__device__ float g_k   [Bn*Cc*HWn];
__device__ float g_att [Bn*Cc*HWn];
__device__ float g_xln [Bn*Cc*HWn];
__device__ float g_t   [Bn*2*HIDn*HWn];       // 356 MB
__device__ float g_g   [Bn*HIDn*HWn];         // 178 MB
__device__ float g_Spart [NSPLIT*Bn*HEADSn*HDn*HDn];
__device__ float g_nqpart[NSPLIT*Bn*Cc];
__device__ float g_nkpart[NSPLIT*Bn*Cc];
__device__ float g_opm [Bn*Cc];
__device__ float g_spm [Bn*Cc];
__device__ float g_probs[Bn*HEADSn*HDn*HDn];
__device__ float g_M   [Bn*Cc*Cc];
__device__ float g_Watt[Bn*Cc*Cc];

// ------------------------- tiny prep: text MLP + argsort + pp ---------------
__global__ void k_prep(const float* __restrict__ text,
                       const float* __restrict__ lin1_w, const float* __restrict__ lin1_b,
                       const float* __restrict__ lin3_w, const float* __restrict__ lin3_b,
                       const float* __restrict__ pp_w,  const float* __restrict__ pp_b)
{
    int b = blockIdx.x;
    int t = threadIdx.x;                       // 512 threads
    __shared__ float s_in[LINn], s_t1[LINn], s_t2[LINn];
    s_in[t] = text[b*LINn + t];
    __syncthreads();
    float a = lin1_b[t];
    for (int i = 0; i < LINn; i++) a += s_in[i] * lin1_w[t*LINn + i];
    s_t1[t] = a;
    __syncthreads();
    a = lin3_b[t];
    for (int i = 0; i < LINn; i++) a += s_t1[i] * lin3_w[t*LINn + i];
    s_t2[t] = a;
    __syncthreads();
    // descending rank, stable (lower index first on ties) == jax.lax.top_k
    float v = s_t2[t];
    int rank = 0;
    for (int i = 0; i < LINn; i++) {
        float u = s_t2[i];
        rank += (u > v) || (u == v && i < t);
    }
    g_idx[b*LINn + rank] = t;
    if (t < MHn) {
        float p = pp_b[t];
        for (int i = 0; i < LINn; i++) p += s_in[i] * pp_w[t*LINn + i];
        g_pp[b*MHn + t] = p;
    }
}

// ------------------------- effective shuffle weight -------------------------
__global__ void k_beff(const float* __restrict__ cow, const float* __restrict__ cob,
                       const float* __restrict__ c1b)
{
    int b = blockIdx.x, o = threadIdx.x;      // 256 threads
    float a = cob[o];
    for (int j = 0; j < 2*Cc; j++) a += cow[o*2*Cc + j] * c1b[g_idx[b*LINn + j]];
    g_beff[b*Cc + o] = a;
}

__global__ void k_weff(const float* __restrict__ cow, const float* __restrict__ c1w)
{
    int b = blockIdx.z;
    int o = blockIdx.y*16 + threadIdx.y;
    int i = blockIdx.x*16 + threadIdx.x;
    __shared__ int sidx[2*Cc];
    int t = threadIdx.y*16 + threadIdx.x;
    sidx[t]       = g_idx[b*LINn + t];
    sidx[t + 256] = g_idx[b*LINn + t + 256];
    __syncthreads();
    float a = 0.f;
    for (int j = 0; j < 2*Cc; j++) a += cow[o*2*Cc + j] * c1w[sidx[j]*Cc + i];
    g_Weff[((long)b*Cc + o)*Cc + i] = a;
}

// ------------------------- generic tiled SGEMM: C = W@X (+bias)(+res) -------
// W: [M,K] row-major (per-batch stride sW), X: [K,N] (stride sX), C: [M,N]
__global__ __launch_bounds__(256)
void k_gemm(const float* __restrict__ Wg, const float* __restrict__ Xg,
            float* __restrict__ Cg, const float* __restrict__ biasg,
            const float* __restrict__ resg,
            int M, int K, int N,
            long sW, long sX, long sC, long sB, long sR)
{
    int bz = blockIdx.z;
    const float* W = Wg + (long)bz*sW;
    const float* X = Xg + (long)bz*sX;
    float*       C = Cg + (long)bz*sC;
    const float* bias = biasg ? biasg + (long)bz*sB : nullptr;
    const float* res  = resg  ? resg  + (long)bz*sR : nullptr;

    int m0 = blockIdx.y*128;
    int n0 = blockIdx.x*128;
    __shared__ float Ws[8][128];
    __shared__ float Xs[8][128];
    int tid = threadIdx.x;
    int tx = tid & 15, ty = tid >> 4;

    float acc[8][8];
#pragma unroll
    for (int i = 0; i < 8; i++)
#pragma unroll
        for (int j = 0; j < 8; j++) acc[i][j] = 0.f;

    int wm = tid >> 1;             // 0..127
    int wk = (tid & 1) * 4;        // 0 or 4
    int xk = tid >> 5;             // 0..7
    int xn = (tid & 31) * 4;       // 0..124

    for (int k0 = 0; k0 < K; k0 += 8) {
        float4 wv;
        if (m0 + wm < M) wv = *(const float4*)(W + (long)(m0 + wm)*K + k0 + wk);
        else             wv = make_float4(0.f, 0.f, 0.f, 0.f);
        Ws[wk+0][wm] = wv.x; Ws[wk+1][wm] = wv.y;
        Ws[wk+2][wm] = wv.z; Ws[wk+3][wm] = wv.w;
        float4 xv = *(const float4*)(X + (long)(k0 + xk)*N + n0 + xn);
        *(float4*)&Xs[xk][xn] = xv;
        __syncthreads();
#pragma unroll
        for (int k = 0; k < 8; k++) {
            float a[8], bb[8];
#pragma unroll
            for (int i = 0; i < 4; i++) { a[i]  = Ws[k][ty*4 + i]; a[i+4]  = Ws[k][64 + ty*4 + i]; }
#pragma unroll
            for (int j = 0; j < 4; j++) { bb[j] = Xs[k][tx*4 + j]; bb[j+4] = Xs[k][64 + tx*4 + j]; }
#pragma unroll
            for (int i = 0; i < 8; i++)
#pragma unroll
                for (int j = 0; j < 8; j++) acc[i][j] += a[i]*bb[j];
        }
        __syncthreads();
    }
#pragma unroll
    for (int i = 0; i < 8; i++) {
        int m = m0 + ((i < 4) ? ty*4 + i : 64 + ty*4 + (i-4));
        if (m >= M) continue;
        float bv = bias ? bias[m] : 0.f;
        float*       crow = C + (long)m*N + n0;
        const float* rrow = res ? res + (long)m*N + n0 : nullptr;
        float4 v;
        v.x = acc[i][0] + bv; v.y = acc[i][1] + bv; v.z = acc[i][2] + bv; v.w = acc[i][3] + bv;
        if (rrow) { float4 r = *(const float4*)(rrow + tx*4);
                    v.x += r.x; v.y += r.y; v.z += r.z; v.w += r.w; }
        *(float4*)(crow + tx*4) = v;
        v.x = acc[i][4] + bv; v.y = acc[i][5] + bv; v.z = acc[i][6] + bv; v.w = acc[i][7] + bv;
        if (rrow) { float4 r = *(const float4*)(rrow + 64 + tx*4);
                    v.x += r.x; v.y += r.y; v.z += r.z; v.w += r.w; }
        *(float4*)(crow + 64 + tx*4) = v;
    }
}

// ------------------------- channel LayerNorm (per pixel over 256 ch) --------
__global__ void k_ln(const float* __restrict__ src, float* __restrict__ dst,
                     const float* __restrict__ w, const float* __restrict__ bias)
{
    int b = blockIdx.y;
    int p = blockIdx.x*blockDim.x + threadIdx.x;   // pixel
    const float* s = src + (long)b*CHW + p;
    float sum = 0.f, sq = 0.f;
    for (int c = 0; c < Cc; c++) { float x = s[(long)c*HWn]; sum += x; sq += x*x; }
    float mu  = sum * (1.f/Cc);
    float var = sq * (1.f/Cc) - mu*mu;
    float rs  = 1.f / sqrtf(var + 1e-5f);
    float* d  = dst + (long)b*CHW + p;
    for (int c = 0; c < Cc; c++) {
        float x = s[(long)c*HWn];
        d[(long)c*HWn] = (x - mu)*rs*w[c] + bias[c];
    }
}

// ------------------------- per-channel mean over HW -------------------------
__global__ void k_chmean(const float* __restrict__ src, float* __restrict__ dst)
{
    int b = blockIdx.y, c = blockIdx.x, t = threadIdx.x;
    const float* s = src + ((long)b*Cc + c)*HWn;
    float a = 0.f;
    for (int i = t; i < HWn; i += 256) a += s[i];
    __shared__ float r[256];
    r[t] = a; __syncthreads();
    for (int o = 128; o > 0; o >>= 1) { if (t < o) r[t] += r[t+o]; __syncthreads(); }
    if (t == 0) dst[b*Cc + c] = r[0] * (1.f/HWn);
}

// ------------------------- per-head QK^T partial + row norms ----------------
__global__ void k_scores(const float* __restrict__ q, const float* __restrict__ k)
{
    int sp = blockIdx.x, h = blockIdx.y, b = blockIdx.z;
    int d = threadIdx.x, c = threadIdx.y;
    int tid = c*32 + d;
    const float* Q  = q + ((long)(b*Cc + h*HDn))*HWn;
    const float* Kp = k + ((long)(b*Cc + h*HDn))*HWn;
    __shared__ float qs[32][65], ks[32][65];
    const int chunk = HWn / NSPLIT;     // 2048
    int n0 = sp*chunk;
    float acc = 0.f, accq = 0.f, acck = 0.f;
    int lr = tid >> 5;
    int lc = (tid & 31) * 2;
    for (int n = n0; n < n0 + chunk; n += 64) {
        float2 qv = *(const float2*)(Q  + (long)lr*HWn + n + lc);
        float2 kv = *(const float2*)(Kp + (long)lr*HWn + n + lc);
        __syncthreads();
        qs[lr][lc] = qv.x; qs[lr][lc+1] = qv.y;
        ks[lr][lc] = kv.x; ks[lr][lc+1] = kv.y;
        __syncthreads();
#pragma unroll 16
        for (int t = 0; t < 64; t++) acc += qs[c][t]*ks[d][t];
        if (d == 0) {
#pragma unroll 16
            for (int t = 0; t < 64; t++) { float v = qs[c][t]; accq += v*v; }
        }
        if (c == 0) {
#pragma unroll 16
            for (int t = 0; t < 64; t++) { float v = ks[d][t]; acck += v*v; }
        }
    }
    g_Spart[(((long)sp*Bn + b)*HEADSn + h)*1024 + tid] = acc;
    if (d == 0) g_nqpart[((long)sp*Bn + b)*Cc + h*HDn + c] = accq;
    if (c == 0) g_nkpart[((long)sp*Bn + b)*Cc + h*HDn + d] = acck;
}

// ------------------------- mask generator + softmax --------------------------
__global__ void k_masksm(const float* __restrict__ fp_w,  const float* __restrict__ fp_b,
                         const float* __restrict__ mg1_w, const float* __restrict__ mg1_b,
                         const float* __restrict__ mg2_w, const float* __restrict__ mg2_b,
                         const float* __restrict__ temp)
{
    int h = blockIdx.x, b = blockIdx.y;
    int t = threadIdx.x;                          // 1024 threads
    __shared__ float comb[64], fin[256], h1[128];
    if (t < 32)           comb[t] = g_opm[b*Cc + h*HDn + t];
    else if (t < 64)      comb[t] = g_spm[b*Cc + h*HDn + (t-32)];
    if (t >= 128 && t < 256) fin[t] = g_pp[b*MHn + (t-128)];
    __syncthreads();
    if (t < 128) {
        float a = fp_b[t];
#pragma unroll 8
        for (int i = 0; i < 64; i++) a += comb[i]*fp_w[t*64 + i];
        fin[t] = a;
    }
    __syncthreads();
    if (t < 128) {
        float a = mg1_b[t];
        for (int i = 0; i < 256; i++) a += fin[i]*mg1_w[t*256 + i];
        h1[t] = fmaxf(a, 0.f);
    }
    __syncthreads();
    float a = mg2_b[t];
    for (int i = 0; i < 128; i++) a += h1[i]*mg2_w[t*128 + i];
    float mg = 1.f / (1.f + expf(-a));

    int c = t >> 5, d = t & 31;
    float s = 0.f, nq = 0.f, nk = 0.f;
#pragma unroll
    for (int sp = 0; sp < NSPLIT; sp++) {
        s  += g_Spart[(((long)sp*Bn + b)*HEADSn + h)*1024 + t];
        nq += g_nqpart[((long)sp*Bn + b)*Cc + h*HDn + c];
        nk += g_nkpart[((long)sp*Bn + b)*Cc + h*HDn + d];
    }
    float val = s / (fmaxf(sqrtf(nq), 1e-12f) * fmaxf(sqrtf(nk), 1e-12f));
    val = val * temp[h] * mg;
    // softmax over d (lane) within warp (warp == row c)
    float m = val;
    for (int o = 16; o > 0; o >>= 1) m = fmaxf(m, __shfl_xor_sync(0xffffffffu, m, o));
    float e = expf(val - m);
    float ssum = e;
    for (int o = 16; o > 0; o >>= 1) ssum += __shfl_xor_sync(0xffffffffu, ssum, o);
    g_probs[((long)b*HEADSn + h)*1024 + t] = e / ssum;
}

// ------------------------- M = o_w · blockdiag(probs) -----------------------
__global__ void k_M(const float* __restrict__ o_w)
{
    int b = blockIdx.x, o = blockIdx.y;
    int col = threadIdx.x;                        // col = h*32 + d
    __shared__ float ow[256];
    __shared__ float pr[HEADSn*HDn*HDn];          // 8192 floats
    ow[col] = o_w[o*Cc + col];
    for (int i = col; i < HEADSn*HDn*HDn; i += 256) pr[i] = g_probs[(long)b*HEADSn*HDn*HDn + i];
    __syncthreads();
    int h = col >> 5, d = col & 31;
    float a = 0.f;
#pragma unroll 8
    for (int c = 0; c < 32; c++) a += ow[h*HDn + c] * pr[h*1024 + c*32 + d];
    g_M[((long)b*Cc + o)*Cc + col] = a;
}

// ------------------------- depthwise 3x3 + exact gelu gate ------------------
__global__ void k_dwgelu(const float* __restrict__ tin, const float* __restrict__ dw)
{
    int x  = blockIdx.x*32 + (threadIdx.x & 31);
    int y  = blockIdx.y*8  + (threadIdx.x >> 5);
    int zc = blockIdx.z;
    int b  = zc / HIDn;
    int c  = zc % HIDn;
    const float* p1 = tin + ((long)b*2*HIDn + c)*HWn;
    const float* p2 = p1 + (long)HIDn*HWn;
    const float* w1 = dw + c*9;
    const float* w2 = dw + (c + HIDn)*9;
    float a1 = 0.f, a2 = 0.f;
#pragma unroll
    for (int ky = 0; ky < 3; ky++) {
        int yy = y + ky - 1;
        if (yy < 0 || yy >= Hh) continue;
#pragma unroll
        for (int kx = 0; kx < 3; kx++) {
            int xx = x + kx - 1;
            if (xx < 0 || xx >= Ww) continue;
            int off = yy*Ww + xx;
            a1 += p1[off]*w1[ky*3 + kx];
            a2 += p2[off]*w2[ky*3 + kx];
        }
    }
    float g = 0.5f*a1*(1.f + erff(a1*0.70710678118654752f));
    g_g[((long)b*HIDn + c)*HWn + y*Ww + x] = g * a2;
}

// ------------------------- vector copy (img2 passthrough) -------------------
__global__ void k_copy(const float* __restrict__ src, float* __restrict__ dst, long n4)
{
    long i = (long)blockIdx.x*blockDim.x + threadIdx.x;
    if (i < n4) ((float4*)dst)[i] = ((const float4*)src)[i];
}

// ----------------------------------------------------------------------------
extern "C" void kernel_launch(void* const* d_in, const int* in_sizes, int n_in,
                              void* d_out, int out_size)
{
    const float* img    = (const float*)d_in[0];
    const float* text   = (const float*)d_in[1];
    const float* lin1_w = (const float*)d_in[2];
    const float* lin1_b = (const float*)d_in[3];
    const float* lin3_w = (const float*)d_in[4];
    const float* lin3_b = (const float*)d_in[5];
    const float* c1w    = (const float*)d_in[6];
    const float* c1b    = (const float*)d_in[7];
    const float* cow    = (const float*)d_in[8];
    const float* cob    = (const float*)d_in[9];
    const float* n1w    = (const float*)d_in[10];
    const float* n1b    = (const float*)d_in[11];
    const float* n2w    = (const float*)d_in[12];
    const float* n2b    = (const float*)d_in[13];
    const float* n3w    = (const float*)d_in[14];
    const float* n3b    = (const float*)d_in[15];
    const float* q_w    = (const float*)d_in[16];
    const float* k_w    = (const float*)d_in[17];
    const float* v_w    = (const float*)d_in[18];
    const float* o_w    = (const float*)d_in[19];
    const float* temp   = (const float*)d_in[20];
    const float* fp_w   = (const float*)d_in[21];
    const float* fp_b   = (const float*)d_in[22];
    const float* pp_w   = (const float*)d_in[23];
    const float* pp_b   = (const float*)d_in[24];
    const float* mg1_w  = (const float*)d_in[25];
    const float* mg1_b  = (const float*)d_in[26];
    const float* mg2_w  = (const float*)d_in[27];
    const float* mg2_b  = (const float*)d_in[28];
    const float* pi_w   = (const float*)d_in[29];
    const float* dw_w   = (const float*)d_in[30];
    const float* po_w   = (const float*)d_in[31];
    float* out = (float*)d_out;

    float *p_Weff, *p_beff, *p_kn, *p_qn, *p_q, *p_k, *p_att, *p_xln, *p_t, *p_g;
    float *p_opm, *p_spm, *p_M, *p_Watt;
    cudaGetSymbolAddress((void**)&p_Weff, g_Weff);
    cudaGetSymbolAddress((void**)&p_beff, g_beff);
    cudaGetSymbolAddress((void**)&p_kn,   g_kn);
    cudaGetSymbolAddress((void**)&p_qn,   g_qn);
    cudaGetSymbolAddress((void**)&p_q,    g_q);
    cudaGetSymbolAddress((void**)&p_k,    g_k);
    cudaGetSymbolAddress((void**)&p_att,  g_att);
    cudaGetSymbolAddress((void**)&p_xln,  g_xln);
    cudaGetSymbolAddress((void**)&p_t,    g_t);
    cudaGetSymbolAddress((void**)&p_g,    g_g);
    cudaGetSymbolAddress((void**)&p_opm,  g_opm);
    cudaGetSymbolAddress((void**)&p_spm,  g_spm);
    cudaGetSymbolAddress((void**)&p_M,    g_M);
    cudaGetSymbolAddress((void**)&p_Watt, g_Watt);

    // 1. text MLP, argsort, pp
    k_prep<<<Bn, LINn>>>(text, lin1_w, lin1_b, lin3_w, lin3_b, pp_w, pp_b);
    // 2. effective shuffle weight/bias
    k_beff<<<Bn, Cc>>>(cow, cob, c1b);
    k_weff<<<dim3(16,16,Bn), dim3(16,16)>>>(cow, c1w);
    // 3. q_in = W_eff @ img + b_eff   -> g_qn (raw), then LN in place
    k_gemm<<<dim3(128,2,Bn), 256>>>(p_Weff, img, p_qn, p_beff, nullptr,
                                    Cc, Cc, HWn, (long)Cc*Cc, CHW, CHW, Cc, 0);
    k_ln<<<dim3(64,Bn), 256>>>(p_qn, p_qn, n1w, n1b);
    k_ln<<<dim3(64,Bn), 256>>>(img,  p_kn, n2w, n2b);
    // 4. q = q_w@qn, k = k_w@kn
    k_gemm<<<dim3(128,2,Bn), 256>>>(q_w, p_qn, p_q, nullptr, nullptr,
                                    Cc, Cc, HWn, 0, CHW, CHW, 0, 0);
    k_gemm<<<dim3(128,2,Bn), 256>>>(k_w, p_kn, p_k, nullptr, nullptr,
                                    Cc, Cc, HWn, 0, CHW, CHW, 0, 0);
    // 5. channel means (op from kn, sp from qn)
    k_chmean<<<dim3(Cc,Bn), 256>>>(p_kn, p_opm);
    k_chmean<<<dim3(Cc,Bn), 256>>>(p_qn, p_spm);
    // 6. per-head scores partials + norms
    k_scores<<<dim3(NSPLIT, HEADSn, Bn), dim3(32,32)>>>(p_q, p_k);
    // 7. mask generator + softmax -> probs
    k_masksm<<<dim3(HEADSn, Bn), 1024>>>(fp_w, fp_b, mg1_w, mg1_b, mg2_w, mg2_b, temp);
    // 8. M = o_w · blockdiag(probs);  W_att = M @ v_w
    k_M<<<dim3(Bn, Cc), 256>>>(o_w);
    k_gemm<<<dim3(2,2,Bn), 256>>>(p_M, v_w, p_Watt, nullptr, nullptr,
                                  Cc, Cc, Cc, (long)Cc*Cc, 0, (long)Cc*Cc, 0, 0);
    // 9. att = W_att @ kn
    k_gemm<<<dim3(128,2,Bn), 256>>>(p_Watt, p_kn, p_att, nullptr, nullptr,
                                    Cc, Cc, HWn, (long)Cc*Cc, CHW, CHW, 0, 0);
    // 10. FFN
    k_ln<<<dim3(64,Bn), 256>>>(p_att, p_xln, n3w, n3b);
    k_gemm<<<dim3(128,11,Bn), 256>>>(pi_w, p_xln, p_t, nullptr, nullptr,
                                     2*HIDn, Cc, HWn, 0, CHW, (long)2*HIDn*HWn, 0, 0);
    k_dwgelu<<<dim3(4,16,Bn*HIDn), 256>>>(p_t, dw_w);
    k_gemm<<<dim3(128,2,Bn), 256>>>(po_w, p_g, out, nullptr, p_att,
                                    Cc, HIDn, HWn, 0, (long)HIDn*HWn, CHW, 0, CHW);
    // 11. second tuple output: img2 passthrough
    if ((long)out_size >= 2*NIMG)
        k_copy<<<16384, 256>>>(img, out + NIMG, NIMG/4);
}